// round 17
// baseline (speedup 1.0000x reference)
#include <cuda_runtime.h>
#include <cuda_bf16.h>
#include <cstdint>

// Problem constants
#define L_DIM 12
#define B_DIM 4
#define H_DIM 12
#define S_DIM 785
#define NP    784             // S-1, LayerNorm width
#define KSC   588             // kth smallest (1-based)
#define NMAPS (L_DIM * H_DIM) // 144 maps per batch
#define NGRP  196             // 784 rows / 4 rows per aligned group
#define NSP   (NMAPS * 2)     // 288 partial slots (2 halves per map)

// Deterministic partial column sums: [batch][slot][column]
__device__ float g_partial[B_DIM][NSP][NP];
// Reduced column means: [batch][column]
__device__ float g_s[B_DIM][NP];

// ---------------------------------------------------------------------------
// Kernel 1: column sums via ALIGNED float4 streaming, HALF-map granularity.
// The stream's (slot -> column) mapping is group-invariant, so a map splits
// cleanly at a group boundary: half 0 = groups [0,98), half 1 = groups
// [98,195) + peel group 195 (which owns the head/tail scalar fixup).
// 1152 blocks (~1.23 MB each) -> 7.8 waves: halves the end-of-kernel DRAM
// drain quantum that capped R13 at 83.6% DRAM.
// Grid: (288 = map*2+half, 4 batches), 256 threads.
// ---------------------------------------------------------------------------
__global__ __launch_bounds__(256) void colsum_kernel(const float* __restrict__ att)
{
    const int slot = blockIdx.x;            // 0..287
    const int m    = slot >> 1;             // 0..143 (l*12+h)
    const int half = slot & 1;
    const int b    = blockIdx.y;            // 0..3
    const int l = m / H_DIM;
    const int h = m % H_DIM;
    const int t = threadIdx.x;              // 0..255

    const size_t SD = (size_t)S_DIM;
    const float* row1 = att + (((size_t)l * B_DIM + b) * H_DIM + h) * (SD * SD) + SD;

    const int off16 = (int)((uintptr_t)row1 & 15);        // 0,4,8,12
    const int phi   = off16 ? (16 - off16) >> 2 : 0;      // 0..3 leading scalars
    const float4* abase = (const float4*)(row1 + phi);

    float a00=0.f,a01=0.f,a02=0.f,a03=0.f;
    float a10=0.f,a11=0.f,a12=0.f,a13=0.f;
    float a20=0.f,a21=0.f,a22=0.f,a23=0.f;
    float a30=0.f,a31=0.f,a32=0.f,a33=0.f;
    const bool has3 = (t < 17);             // slots 768..784

    const float4* p = abase + (half ? (size_t)98 * 785 : 0);
    const int nfull = half ? 97 : 98;       // half1 keeps the peel

    #pragma unroll 2
    for (int g = 0; g < nfull; ++g) {
        float4 v0 = __ldcs(p + t);
        float4 v1 = __ldcs(p + t + 256);
        float4 v2 = __ldcs(p + t + 512);
        a00+=v0.x; a01+=v0.y; a02+=v0.z; a03+=v0.w;
        a10+=v1.x; a11+=v1.y; a12+=v1.z; a13+=v1.w;
        a20+=v2.x; a21+=v2.y; a22+=v2.z; a23+=v2.w;
        if (has3) {
            float4 v3 = __ldcs(p + t + 768);
            a30+=v3.x; a31+=v3.y; a32+=v3.z; a33+=v3.w;
        }
        p += 785;
    }

    // ---- peel group 195 (half 1 only): slot 784's top phi lanes would read
    // past the map; they take the phi leading scalars instead. ----
    if (half) {
        float4 v0 = __ldcs(p + t);
        float4 v1 = __ldcs(p + t + 256);
        float4 v2 = __ldcs(p + t + 512);
        a00+=v0.x; a01+=v0.y; a02+=v0.z; a03+=v0.w;
        a10+=v1.x; a11+=v1.y; a12+=v1.z; a13+=v1.w;
        a20+=v2.x; a21+=v2.y; a22+=v2.z; a23+=v2.w;
        if (t < 16) {
            float4 v3 = __ldcs(p + t + 768);
            a30+=v3.x; a31+=v3.y; a32+=v3.z; a33+=v3.w;
        } else if (t == 16) {
            const float* tail = (const float*)(p + 784);
            const float* head = ((const float*)abase) - 4;
            float w0 = (0 < 4 - phi) ? tail[0] : head[0];
            float w1 = (1 < 4 - phi) ? tail[1] : head[1];
            float w2 = (2 < 4 - phi) ? tail[2] : head[2];
            float w3 = (3 < 4 - phi) ? tail[3] : head[3];
            a30+=w0; a31+=w1; a32+=w2; a33+=w3;
        }
    }

    // ---- fold the 4 row-phases per column via shared (exclusive slots) ----
    __shared__ float sq[4 * S_DIM];         // 3140 floats
    {
        int q0 = phi + 4 * t;
        sq[q0+0]=a00; sq[q0+1]=a01; sq[q0+2]=a02; sq[q0+3]=a03;
        int q1 = phi + 4 * (t + 256);
        sq[q1+0]=a10; sq[q1+1]=a11; sq[q1+2]=a12; sq[q1+3]=a13;
        int q2 = phi + 4 * (t + 512);
        sq[q2+0]=a20; sq[q2+1]=a21; sq[q2+2]=a22; sq[q2+3]=a23;
        if (has3) {
            int q3 = phi + 4 * (t + 768);   // may wrap past 3140 for t==16
            int w;
            w = q3+0; if (w >= 4*S_DIM) w -= 4*S_DIM; sq[w]=a30;
            w = q3+1; if (w >= 4*S_DIM) w -= 4*S_DIM; sq[w]=a31;
            w = q3+2; if (w >= 4*S_DIM) w -= 4*S_DIM; sq[w]=a32;
            w = q3+3; if (w >= 4*S_DIM) w -= 4*S_DIM; sq[w]=a33;
        }
    }
    __syncthreads();

    #pragma unroll
    for (int c = t; c < S_DIM; c += 256) {
        if (c == 0) continue;               // CLS column dropped
        float sum = (sq[c] + sq[c + S_DIM]) + (sq[c + 2*S_DIM] + sq[c + 3*S_DIM]);
        g_partial[b][slot][c - 1] = sum;
    }
}

// ---------------------------------------------------------------------------
// Kernel 2: partial-matrix reduction over 288 slots, spread across 32 blocks
// (8 x 98 threads per batch). Deterministic order, unroll-16 for MLP.
// ---------------------------------------------------------------------------
__global__ __launch_bounds__(98) void reduce_kernel()
{
    const int b = blockIdx.y;
    const int j = blockIdx.x * 98 + threadIdx.x;   // 0..783

    float s = 0.f;
    #pragma unroll 16
    for (int q = 0; q < NSP; ++q)
        s += g_partial[b][q][j];
    g_s[b][j] = s * (1.0f / (float)NMAPS);
}

// ---------------------------------------------------------------------------
// Kernel 3: fused LayerNorm + sigmoid + exact kth-smallest + mask.
// kth-smallest via bit-pattern bisection with one __syncthreads_count
// (BAR.RED.POPC) per iteration — bit-exact vs sort(p)[KSC-1].
// Grid B x 800 threads (784..799 inert padding, pb=+inf never counted).
// ---------------------------------------------------------------------------
#define EPI_T 800

__global__ __launch_bounds__(EPI_T) void epilogue_kernel(const float* __restrict__ gamma,
                                                         const float* __restrict__ beta,
                                                         float* __restrict__ out)
{
    const int b   = blockIdx.x;
    const int tid = threadIdx.x;            // 0..799
    const bool act = (tid < NP);

    __shared__ float red[1024];

    const float s = act ? g_s[b][tid] : 0.f;

    // zero padding region of the tree
    if (tid >= NP) red[tid] = 0.f;
    if (tid < 1024 - EPI_T) red[EPI_T + tid] = 0.f;

    // --- pass 1: mean ---
    if (act) red[tid] = s;
    __syncthreads();
    for (int st = 512; st > 0; st >>= 1) {
        if (tid < st) red[tid] += red[tid + st];
        __syncthreads();
    }
    const float mean = red[0] * (1.0f / (float)NP);
    __syncthreads();

    // --- pass 2: variance ---
    const float d = act ? (s - mean) : 0.f;
    red[tid] = d * d;
    __syncthreads();
    for (int st = 512; st > 0; st >>= 1) {
        if (tid < st) red[tid] += red[tid + st];
        __syncthreads();
    }
    const float var = red[0] * (1.0f / (float)NP);

    // ---- LayerNorm + sigmoid ----
    float pv = 0.f;
    unsigned pb = 0x7F800000u;              // +inf for padding: never counted
    if (act) {
        const float ln = d * rsqrtf(var + 1e-5f) * gamma[tid] + beta[tid];
        pv = 1.0f / (1.0f + expf(-ln));
        pb = __float_as_uint(pv);           // positive -> monotone bits
    }

    // ---- bisection on bit pattern: smallest v with count(pb<=v) >= KSC ----
    unsigned lo = 0u, hi = 0x3F800000u;     // p in (0, 1.0]
    while (lo < hi) {                       // ~30 uniform iterations
        const unsigned mid = (lo + hi) >> 1;
        const int cnt = __syncthreads_count(pb <= mid);
        if (cnt >= KSC) hi = mid; else lo = mid + 1;
    }
    const float thr = __uint_as_float(lo);  // == sort(p)[KSC-1], bit-exact

    // ---- mask ----
    if (act)
        out[b * NP + tid] = (pv > thr) ? 1.0f : 0.0f;
}

// ---------------------------------------------------------------------------
extern "C" void kernel_launch(void* const* d_in, const int* in_sizes, int n_in,
                              void* d_out, int out_size)
{
    const float* att   = (const float*)d_in[0];
    const float* gamma = (const float*)d_in[1];
    const float* beta  = (const float*)d_in[2];
    float* out = (float*)d_out;

    colsum_kernel<<<dim3(NSP, B_DIM), 256>>>(att);
    reduce_kernel<<<dim3(8, B_DIM), 98>>>();
    epilogue_kernel<<<B_DIM, EPI_T>>>(gamma, beta, out);
}